// round 3
// baseline (speedup 1.0000x reference)
#include <cuda_runtime.h>
#include <cuda_bf16.h>
#include <cstdint>

// BitLevelMapper: B=4194304 rows x 16 bits.
// bits:   [B,16] int32 {0,1}  (d_in[0])
// tables: [16, 32768] float32 {0,1} (d_in[1])
// out:    [B,16] float32
//
// R3: ballot-based table pack (one warp per packed word, ~3us vs ~10us);
// map kernel gets __ldcs/__stcs streaming hints, unroll-4 front-batched
// loads for MLP, and LOP-based bit->float conversion instead of I2F.

#define NBITS   16
#define TSIZE   32768           // 2^15 entries per table row
#define NWORDS  2052            // sum over i of ceil(max(2^i,32)/32)

__device__ uint32_t g_packed[NWORDS];

// word offset of table row i in the packed layout
__host__ __device__ __forceinline__ int tab_off(int i) {
    return (i < 5) ? i : ((1 << (i - 5)) + 4);
}

// One warp per packed word: lane b reads entry lw*32+b, ballot packs.
__global__ void pack_tables_kernel(const float* __restrict__ tables) {
    int gw   = (blockIdx.x * blockDim.x + threadIdx.x) >> 5;
    int lane = threadIdx.x & 31;
    if (gw >= NWORDS) return;
    int i = 0;
    #pragma unroll
    for (int r = 1; r < 16; r++)
        if (gw >= tab_off(r)) i = r;
    int lw = gw - tab_off(i);
    float v = tables[(size_t)i * TSIZE + lw * 32 + lane];
    unsigned word = __ballot_sync(0xffffffffu, v != 0.0f);
    if (lane == 0) g_packed[gw] = word;
}

#define MAP_BLOCKS  2048
#define MAP_THREADS 256

__global__ void __launch_bounds__(MAP_THREADS)
map_kernel(const int4* __restrict__ bits4, float4* __restrict__ out4, int nquads) {
    __shared__ uint32_t s_tab[NWORDS];
    for (int t = threadIdx.x; t < NWORDS; t += blockDim.x)
        s_tab[t] = g_packed[t];
    __syncthreads();

    const int stride = gridDim.x * blockDim.x;
    const int base   = blockIdx.x * blockDim.x + threadIdx.x;
    const int q      = base & 3;           // quarter within row (lane-group pos)
    const int shift  = 15 - 4 * q;         // bit position of v.x in pattern P
    const int ii     = 15 - 4 * q;         // table row for m=0

    const int nmain = nquads / stride;     // full iterations (no tail divergence)

    #pragma unroll 4
    for (int it = 0; it < nmain; it++) {
        int t = base + it * stride;
        int4 v = __ldcs(bits4 + t);

        // partial 16-bit pattern: bit j (array order) sits at position 15-j
        unsigned P = ((unsigned)v.x << shift)       | ((unsigned)v.y << (shift - 1))
                   | ((unsigned)v.z << (shift - 2)) | ((unsigned)v.w << (shift - 3));
        // OR-reduce across the aligned 4-lane group -> full pattern in all 4 lanes
        P |= __shfl_xor_sync(0xffffffffu, P, 1);
        P |= __shfl_xor_sync(0xffffffffu, P, 2);

        float o[4];
        #pragma unroll
        for (int m = 0; m < 4; m++) {
            int i = ii - m;
            unsigned addr = P & ((1u << i) - 1u);          // prefix of context
            uint32_t wv = s_tab[tab_off(i) + (addr >> 5)];
            unsigned x = ((wv >> (addr & 31u)) ^ (P >> i)) & 1u;   // bit ^ flip
            o[m] = __uint_as_float((0u - x) & 0x3f800000u);        // x ? 1.0f : 0.0f
        }
        __stcs(out4 + t, make_float4(o[0], o[1], o[2], o[3]));
    }

    // tail (not taken for B=4194304; kept for safety, no shuffles here)
    for (int t = base + nmain * stride; t < nquads; t += stride) {
        int row = t >> 2, qq = t & 3;
        const int4* rp = bits4 + (size_t)row * 4;
        int4 r0 = rp[0], r1 = rp[1], r2 = rp[2], r3 = rp[3];
        int b[16] = { r0.x, r0.y, r0.z, r0.w, r1.x, r1.y, r1.z, r1.w,
                      r2.x, r2.y, r2.z, r2.w, r3.x, r3.y, r3.z, r3.w };
        unsigned P = 0;
        #pragma unroll
        for (int j = 0; j < 16; j++) P |= ((unsigned)b[j] & 1u) << (15 - j);
        float o[4];
        #pragma unroll
        for (int m = 0; m < 4; m++) {
            int i = 15 - (4 * qq + m);
            unsigned addr = P & ((1u << i) - 1u);
            uint32_t wv = s_tab[tab_off(i) + (addr >> 5)];
            unsigned x = ((wv >> (addr & 31u)) ^ (P >> i)) & 1u;
            o[m] = __uint_as_float((0u - x) & 0x3f800000u);
        }
        out4[t] = make_float4(o[0], o[1], o[2], o[3]);
    }
}

extern "C" void kernel_launch(void* const* d_in, const int* in_sizes, int n_in,
                              void* d_out, int out_size) {
    const int4*  bits4  = (const int4*)d_in[0];
    const float* tables = (const float*)d_in[1];
    float4*      out4   = (float4*)d_out;

    int nquads = in_sizes[0] / 4;      // 16777216

    pack_tables_kernel<<<(NWORDS * 32 + 255) / 256, 256>>>(tables);
    map_kernel<<<MAP_BLOCKS, MAP_THREADS>>>(bits4, out4, nquads);
}

// round 4
// speedup vs baseline: 1.0560x; 1.0560x over previous
#include <cuda_runtime.h>
#include <cuda_bf16.h>
#include <cstdint>

// BitLevelMapper: B=4194304 rows x 16 bits.
// bits:   [B,16] int32 {0,1}  (d_in[0])
// tables: [16, 32768] float32 {0,1} (d_in[1])
// out:    [B,16] float32
//
// R4: R2 map structure + ballot-based pack + LOP bit->float + explicit
// depth-2 software pipeline (prefetch next int4 before current chain) so
// each warp keeps 2 LDG.128 in flight. No pragma unroll, no .cs hints.

#define NBITS   16
#define TSIZE   32768           // 2^15 entries per table row
#define NWORDS  2052            // sum over i of ceil(max(2^i,32)/32)

__device__ uint32_t g_packed[NWORDS];

// word offset of table row i in the packed layout
__host__ __device__ __forceinline__ int tab_off(int i) {
    return (i < 5) ? i : ((1 << (i - 5)) + 4);
}

// One warp per packed word: lane b reads entry lw*32+b, ballot packs.
__global__ void pack_tables_kernel(const float* __restrict__ tables) {
    int gw   = (blockIdx.x * blockDim.x + threadIdx.x) >> 5;
    int lane = threadIdx.x & 31;
    if (gw >= NWORDS) return;
    int i = 0;
    #pragma unroll
    for (int r = 1; r < 16; r++)
        if (gw >= tab_off(r)) i = r;
    int lw = gw - tab_off(i);
    float v = tables[(size_t)i * TSIZE + lw * 32 + lane];
    unsigned word = __ballot_sync(0xffffffffu, v != 0.0f);
    if (lane == 0) g_packed[gw] = word;
}

#define MAP_BLOCKS  2048
#define MAP_THREADS 256

__device__ __forceinline__ void process_quad(
    int4 v, int shift, int ii, const uint32_t* s_tab, float4* dst)
{
    // partial 16-bit pattern: bit j (array order) sits at position 15-j
    unsigned P = ((unsigned)v.x << shift)       | ((unsigned)v.y << (shift - 1))
               | ((unsigned)v.z << (shift - 2)) | ((unsigned)v.w << (shift - 3));
    // OR-reduce across the aligned 4-lane group -> full pattern in all 4 lanes
    P |= __shfl_xor_sync(0xffffffffu, P, 1);
    P |= __shfl_xor_sync(0xffffffffu, P, 2);

    float o[4];
    #pragma unroll
    for (int m = 0; m < 4; m++) {
        int i = ii - m;
        unsigned addr = P & ((1u << i) - 1u);              // prefix of context
        uint32_t wv = s_tab[tab_off(i) + (addr >> 5)];
        unsigned x = ((wv >> (addr & 31u)) ^ (P >> i)) & 1u;   // bit ^ flip
        o[m] = __uint_as_float((0u - x) & 0x3f800000u);        // x ? 1.0f : 0.0f
    }
    *dst = make_float4(o[0], o[1], o[2], o[3]);
}

__global__ void __launch_bounds__(MAP_THREADS, 6)
map_kernel(const int4* __restrict__ bits4, float4* __restrict__ out4, int nquads) {
    __shared__ uint32_t s_tab[NWORDS];
    for (int t = threadIdx.x; t < NWORDS; t += blockDim.x)
        s_tab[t] = g_packed[t];
    __syncthreads();

    const int stride = gridDim.x * blockDim.x;
    const int base   = blockIdx.x * blockDim.x + threadIdx.x;
    const int q      = base & 3;            // quarter within row (lane-group pos)
    const int shift  = 15 - 4 * q;          // bit position of v.x in pattern P

    const int nmain  = nquads / stride;     // full iterations (no tail divergence)

    if (nmain > 0) {
        int  t = base;
        int4 v = bits4[t];                   // pipeline prologue
        for (int it = 1; it < nmain; it++) {
            int4 vn = bits4[t + stride];     // prefetch next (in flight w/ chain)
            process_quad(v, shift, shift, s_tab, &out4[t]);
            t += stride;
            v = vn;
        }
        process_quad(v, shift, shift, s_tab, &out4[t]);   // epilogue
    }

    // tail (not taken for B=4194304; kept for safety, no shuffles here)
    for (int t = base + nmain * stride; t < nquads; t += stride) {
        int row = t >> 2, qq = t & 3;
        const int4* rp = bits4 + (size_t)row * 4;
        int4 r0 = rp[0], r1 = rp[1], r2 = rp[2], r3 = rp[3];
        int b[16] = { r0.x, r0.y, r0.z, r0.w, r1.x, r1.y, r1.z, r1.w,
                      r2.x, r2.y, r2.z, r2.w, r3.x, r3.y, r3.z, r3.w };
        unsigned P = 0;
        #pragma unroll
        for (int j = 0; j < 16; j++) P |= ((unsigned)b[j] & 1u) << (15 - j);
        float o[4];
        #pragma unroll
        for (int m = 0; m < 4; m++) {
            int i = 15 - (4 * qq + m);
            unsigned addr = P & ((1u << i) - 1u);
            uint32_t wv = s_tab[tab_off(i) + (addr >> 5)];
            unsigned x = ((wv >> (addr & 31u)) ^ (P >> i)) & 1u;
            o[m] = __uint_as_float((0u - x) & 0x3f800000u);
        }
        out4[t] = make_float4(o[0], o[1], o[2], o[3]);
    }
}

extern "C" void kernel_launch(void* const* d_in, const int* in_sizes, int n_in,
                              void* d_out, int out_size) {
    const int4*  bits4  = (const int4*)d_in[0];
    const float* tables = (const float*)d_in[1];
    float4*      out4   = (float4*)d_out;

    int nquads = in_sizes[0] / 4;      // 16777216

    pack_tables_kernel<<<(NWORDS * 32 + 255) / 256, 256>>>(tables);
    map_kernel<<<MAP_BLOCKS, MAP_THREADS>>>(bits4, out4, nquads);
}

// round 5
// speedup vs baseline: 1.1545x; 1.0934x over previous
#include <cuda_runtime.h>
#include <cuda_bf16.h>
#include <cstdint>

// BitLevelMapper: B=4194304 rows x 16 bits.
// bits:   [B,16] int32 {0,1}  (d_in[0])
// tables: [16, 32768] float32 {0,1} (d_in[1])
// out:    [B,16] float32
//
// R5: exact R2 map body (32 regs -> 8 CTAs/SM) + ballot pack + LOP
// bit->float. Grid = 1216 blocks (152 SMs x 8 CTAs) = ONE full resident
// wave, eliminating R2's 73%-fill second wave (occ 82% -> ~95%).

#define NBITS   16
#define TSIZE   32768           // 2^15 entries per table row
#define NWORDS  2052            // sum over i of ceil(max(2^i,32)/32)

__device__ uint32_t g_packed[NWORDS];

// word offset of table row i in the packed layout
__host__ __device__ __forceinline__ int tab_off(int i) {
    return (i < 5) ? i : ((1 << (i - 5)) + 4);
}

// One warp per packed word: lane b reads entry lw*32+b, ballot packs.
__global__ void pack_tables_kernel(const float* __restrict__ tables) {
    int gw   = (blockIdx.x * blockDim.x + threadIdx.x) >> 5;
    int lane = threadIdx.x & 31;
    if (gw >= NWORDS) return;
    int i = 0;
    #pragma unroll
    for (int r = 1; r < 16; r++)
        if (gw >= tab_off(r)) i = r;
    int lw = gw - tab_off(i);
    float v = tables[(size_t)i * TSIZE + lw * 32 + lane];
    unsigned word = __ballot_sync(0xffffffffu, v != 0.0f);
    if (lane == 0) g_packed[gw] = word;
}

#define MAP_BLOCKS  1216        // 152 SMs x 8 CTAs: one full resident wave
#define MAP_THREADS 256

__global__ void __launch_bounds__(MAP_THREADS, 8)
map_kernel(const int4* __restrict__ bits4, float4* __restrict__ out4, int nquads) {
    __shared__ uint32_t s_tab[NWORDS];
    for (int t = threadIdx.x; t < NWORDS; t += blockDim.x)
        s_tab[t] = g_packed[t];
    __syncthreads();

    const int stride = gridDim.x * blockDim.x;
    const int base   = blockIdx.x * blockDim.x + threadIdx.x;
    const int q      = base & 3;            // quarter within row (lane-group pos)
    const int shift  = 15 - 4 * q;          // bit position of v.x in pattern P

    const int nmain  = nquads / stride;     // uniform across all threads

    for (int it = 0; it < nmain; it++) {
        int t = base + it * stride;
        int4 v = bits4[t];

        // partial 16-bit pattern: bit j (array order) sits at position 15-j
        unsigned P = ((unsigned)v.x << shift)       | ((unsigned)v.y << (shift - 1))
                   | ((unsigned)v.z << (shift - 2)) | ((unsigned)v.w << (shift - 3));
        // OR-reduce across the aligned 4-lane group -> full pattern in all 4 lanes
        P |= __shfl_xor_sync(0xffffffffu, P, 1);
        P |= __shfl_xor_sync(0xffffffffu, P, 2);

        float o[4];
        #pragma unroll
        for (int m = 0; m < 4; m++) {
            int i = shift - m;                             // table row index
            unsigned addr = P & ((1u << i) - 1u);          // prefix of context
            uint32_t wv = s_tab[tab_off(i) + (addr >> 5)];
            unsigned x = ((wv >> (addr & 31u)) ^ (P >> i)) & 1u;   // bit ^ flip
            o[m] = __uint_as_float((0u - x) & 0x3f800000u);        // x ? 1.0f : 0.0f
        }
        out4[t] = make_float4(o[0], o[1], o[2], o[3]);
    }

    // tail: remaining quads (scalar per-row path, no shuffles; ~1.7% of work)
    for (int t = base + nmain * stride; t < nquads; t += stride) {
        int row = t >> 2, qq = t & 3;
        const int4* rp = bits4 + (size_t)row * 4;
        int4 r0 = rp[0], r1 = rp[1], r2 = rp[2], r3 = rp[3];
        int b[16] = { r0.x, r0.y, r0.z, r0.w, r1.x, r1.y, r1.z, r1.w,
                      r2.x, r2.y, r2.z, r2.w, r3.x, r3.y, r3.z, r3.w };
        unsigned P = 0;
        #pragma unroll
        for (int j = 0; j < 16; j++) P |= ((unsigned)b[j] & 1u) << (15 - j);
        float o[4];
        #pragma unroll
        for (int m = 0; m < 4; m++) {
            int i = 15 - (4 * qq + m);
            unsigned addr = P & ((1u << i) - 1u);
            uint32_t wv = s_tab[tab_off(i) + (addr >> 5)];
            unsigned x = ((wv >> (addr & 31u)) ^ (P >> i)) & 1u;
            o[m] = __uint_as_float((0u - x) & 0x3f800000u);
        }
        out4[t] = make_float4(o[0], o[1], o[2], o[3]);
    }
}

extern "C" void kernel_launch(void* const* d_in, const int* in_sizes, int n_in,
                              void* d_out, int out_size) {
    const int4*  bits4  = (const int4*)d_in[0];
    const float* tables = (const float*)d_in[1];
    float4*      out4   = (float4*)d_out;

    int nquads = in_sizes[0] / 4;      // 16777216

    pack_tables_kernel<<<(NWORDS * 32 + 255) / 256, 256>>>(tables);
    map_kernel<<<MAP_BLOCKS, MAP_THREADS>>>(bits4, out4, nquads);
}